// round 15
// baseline (speedup 1.0000x reference)
#include <cuda_runtime.h>
#include <cuda_fp16.h>
#include <math.h>
#include <stdint.h>

#define B_      8
#define C_      192
#define C3      576
#define HW      16384
#define HEADS_  4
#define HC      48
#define NCHUNK  128
#define GCHUNKS 32
#define NPART   32
#define PART_STRIDE 2400
#define TILE_U4 2304   // uint4 per 96-row x 192-k packed A tile

// -------- device scratch --------
__device__ __half  g_qkv [(size_t)B_ * C3 * HW];
__device__ __half  g_dwq [(size_t)B_ * C3 * HW];
__device__ float   g_part[(size_t)NPART * 32 * PART_STRIDE];
__device__ float   g_gram[32 * HC * HC];
__device__ float   g_nq  [32 * HC];
__device__ float   g_nk  [32 * HC];
__device__ float   g_attn[32 * HC * HC];
__device__ uint4   g_wqkvh[6 * TILE_U4];
__device__ uint4   g_weffh[B_ * 2 * TILE_U4];

// ============================================================
__device__ __forceinline__ void mma_f16(float* d, const uint32_t* a,
                                        uint32_t b0, uint32_t b1) {
    asm volatile(
        "mma.sync.aligned.m16n8k16.row.col.f32.f16.f16.f32 "
        "{%0,%1,%2,%3}, {%4,%5,%6,%7}, {%8,%9}, {%0,%1,%2,%3};\n"
        : "+f"(d[0]), "+f"(d[1]), "+f"(d[2]), "+f"(d[3])
        : "r"(a[0]), "r"(a[1]), "r"(a[2]), "r"(a[3]),
          "r"(b0), "r"(b1));
}

__device__ __forceinline__ __half2 f2h2(float a, float b) {
    return __float22half2_rn(make_float2(a, b));
}

__device__ __forceinline__ uint32_t h2u(__half2 h) {
    union { __half2 h; uint32_t u; } c; c.h = h; return c.u;
}

// ============================================================
// Pack W_qkv (576x192 fp32) -> fragment-uint4 layout.
// ============================================================
__global__ __launch_bounds__(256) void pack_w_kernel(const float* __restrict__ w)
{
    const int idx = blockIdx.x * 256 + threadIdx.x;
    if (idx >= 6 * TILE_U4) return;
    const int mtile = idx / TILE_U4;
    const int rem   = idx % TILE_U4;
    const int lane  = rem & 31;
    int t = rem >> 5;
    const int wmh = t & 1;  t >>= 1;
    const int mt  = t % 3;
    const int it  = t / 3;
    const int grp = lane >> 2, qd = lane & 3;

    const int m   = mtile * 96 + wmh * 48 + mt * 16 + grp;
    const int k2a = it * 8 + qd;
    const int k2b = k2a + 4;

    uint4 o;
    o.x = h2u(f2h2(w[m * C_ + 2 * k2a],       w[m * C_ + 2 * k2a + 1]));
    o.y = h2u(f2h2(w[(m + 8) * C_ + 2 * k2a], w[(m + 8) * C_ + 2 * k2a + 1]));
    o.z = h2u(f2h2(w[m * C_ + 2 * k2b],       w[m * C_ + 2 * k2b + 1]));
    o.w = h2u(f2h2(w[(m + 8) * C_ + 2 * k2b], w[(m + 8) * C_ + 2 * k2b + 1]));
    g_wqkvh[idx] = o;
}

// ============================================================
// Tensor-core GEMM: C = A_packed @ B[b](192xN), N=HW.
// BM=96 BN=128 BK=16. 256 threads / 8 warps (2M x 4N), warp tile 48x32.
// A: coalesced LDG.128 double-buffered 1 ahead (L1-broadcast across warps).
// B: LDG issued 2 iterations ahead of its STS (distance-2 prefetch).
// 2 blocks/SM -> 16 warps/SM for latency hiding.
// ============================================================
#define BM 96
#define BN 128
#define BSX 136

template <bool B_HALF, bool OUT_HALF>
__global__ __launch_bounds__(256, 2) void gemm_f16(
    const uint4* __restrict__ Apk, const void* __restrict__ Bv,
    void* __restrict__ Cv, size_t sAb4, size_t sBb, size_t sCb)
{
    __shared__ __half2 Bsh[2][8][BSX];

    const int N = HW;
    const int n0 = blockIdx.y * BN;

    const int tid  = threadIdx.x;
    const int warp = tid >> 5;
    const int lane = tid & 31;
    const int wmh = warp & 1;             // 0,1 -> M half (48 rows)
    const int wn  = (warp >> 1) * 32;     // 0,32,64,96 -> N quarter
    const int grp = lane >> 2;
    const int qd  = lane & 3;

    const uint4* Ap = Apk + (size_t)blockIdx.z * sAb4 + (size_t)blockIdx.x * TILE_U4;

    // B loader: 256 threads cover [8 k2-rows][128 n] with 4 cols each
    const int bk2 = tid >> 5;            // 0..7
    const int bnc = (lane) << 2;         // 0..124

    const float*  Bf = (const float*)Bv + (size_t)blockIdx.z * sBb;
    const __half* Bh = (const __half*)Bv + (size_t)blockIdx.z * sBb;

    float4 bRegF[2];
    uint2  bRegH[2];
    uint4  aBuf[2][3];

    auto loadG = [&](int k0) {
        if (B_HALF) {
            bRegH[0] = *(const uint2*)&Bh[(size_t)(k0 + 2 * bk2)     * N + n0 + bnc];
            bRegH[1] = *(const uint2*)&Bh[(size_t)(k0 + 2 * bk2 + 1) * N + n0 + bnc];
        } else {
            bRegF[0] = *(const float4*)&Bf[(size_t)(k0 + 2 * bk2)     * N + n0 + bnc];
            bRegF[1] = *(const float4*)&Bf[(size_t)(k0 + 2 * bk2 + 1) * N + n0 + bnc];
        }
    };

    auto loadA = [&](int it, uint4* dst) {
#pragma unroll
        for (int mt = 0; mt < 3; mt++)
            dst[mt] = __ldg(&Ap[((it * 3 + mt) * 2 + wmh) * 32 + lane]);
    };

    auto storeS = [&](int buf) {
        __half2 h[4];
        if (B_HALF) {
            const __half* h0 = (const __half*)&bRegH[0];
            const __half* h1 = (const __half*)&bRegH[1];
#pragma unroll
            for (int j = 0; j < 4; j++) h[j] = __halves2half2(h0[j], h1[j]);
        } else {
            const float* r0 = (const float*)&bRegF[0];
            const float* r1 = (const float*)&bRegF[1];
#pragma unroll
            for (int j = 0; j < 4; j++) h[j] = f2h2(r0[j], r1[j]);
        }
        *(uint4*)&Bsh[buf][bk2][bnc] = *(uint4*)&h[0];
    };

    float acc[3][4][4];
#pragma unroll
    for (int i = 0; i < 3; i++)
#pragma unroll
        for (int j = 0; j < 4; j++)
#pragma unroll
            for (int r = 0; r < 4; r++) acc[i][j][r] = 0.f;

    // prologue: buffer 0 filled; LDG for k-step 1 in flight
    loadG(0);
    storeS(0);
    loadA(0, aBuf[0]);
    loadG(16);
    __syncthreads();

#pragma unroll 2
    for (int it = 0; it < 12; it++) {
        const int cur = it & 1;
        const int nxt = cur ^ 1;
        if (it + 1 < 12) loadA(it + 1, aBuf[nxt]);

#pragma unroll
        for (int nt = 0; nt < 4; nt++) {
            const int n = wn + nt * 8 + grp;
            const uint32_t b0 = *(const uint32_t*)&Bsh[cur][qd    ][n];
            const uint32_t b1 = *(const uint32_t*)&Bsh[cur][qd + 4][n];
#pragma unroll
            for (int mt = 0; mt < 3; mt++)
                mma_f16(acc[mt][nt], (const uint32_t*)&aBuf[cur][mt], b0, b1);
        }

        if (it + 1 < 12) {
            storeS(nxt);                       // LDG issued 1 iteration ago
            if (it + 2 < 12) loadG((it + 2) * 16);  // distance-2 prefetch
            __syncthreads();
        }
    }

    const int m0 = blockIdx.x * BM;
    const int wm = wmh * 48;
    if (OUT_HALF) {
        __half* Ch = (__half*)Cv + (size_t)blockIdx.z * sCb;
#pragma unroll
        for (int mt = 0; mt < 3; mt++) {
#pragma unroll
            for (int nt = 0; nt < 4; nt++) {
                const int row = m0 + wm + mt * 16 + grp;
                const int col = n0 + wn + nt * 8 + qd * 2;
                *(__half2*)&Ch[(size_t)row * N + col] =
                    f2h2(acc[mt][nt][0], acc[mt][nt][1]);
                *(__half2*)&Ch[(size_t)(row + 8) * N + col] =
                    f2h2(acc[mt][nt][2], acc[mt][nt][3]);
            }
        }
    } else {
        float* Cf = (float*)Cv + (size_t)blockIdx.z * sCb;
#pragma unroll
        for (int mt = 0; mt < 3; mt++) {
#pragma unroll
            for (int nt = 0; nt < 4; nt++) {
                const int row = m0 + wm + mt * 16 + grp;
                const int col = n0 + wn + nt * 8 + qd * 2;
                *(float2*)&Cf[(size_t)row * N + col]       = make_float2(acc[mt][nt][0], acc[mt][nt][1]);
                *(float2*)&Cf[(size_t)(row + 8) * N + col] = make_float2(acc[mt][nt][2], acc[mt][nt][3]);
            }
        }
    }
}

// ============================================================
__global__ void noop_kernel() {}

// ============================================================
// Depthwise 3x3 SAME, fp16 smem tile (66x136 halves), fp32 compute.
// ============================================================
__global__ __launch_bounds__(256) void dwconv_kernel(const float* __restrict__ wdw)
{
    __shared__ __half s[66][136];

    const int half_ = blockIdx.x;
    const int ch    = blockIdx.y;
    const int b     = blockIdx.z;
    const int r0    = half_ * 64;

    const __half* in = g_qkv + ((size_t)b * C3 + ch) * HW;
    __half* outp = g_dwq + ((size_t)b * C3 + ch) * HW;
    const int tid = threadIdx.x;

    const uint4 z4 = make_uint4(0, 0, 0, 0);
    for (int i = tid; i < 66 * 16; i += 256) {
        const int sr = i >> 4;
        const int c8 = (i & 15) << 3;
        const int gr = r0 - 1 + sr;
        uint4 v = (gr >= 0 && gr < 128) ? *(const uint4*)&in[gr * 128 + c8] : z4;
        *(uint4*)&s[sr][c8] = v;
    }
    __syncthreads();

    float w[9];
#pragma unroll
    for (int i = 0; i < 9; i++) w[i] = __ldg(&wdw[ch * 9 + i]);

    const int lane = tid & 31;
    const int rb   = tid >> 5;

#pragma unroll
    for (int seg = 0; seg < 4; seg++) {
        const int c = lane + seg * 32;
        float o[8];
#pragma unroll
        for (int rr = 0; rr < 10; rr++) {
            const int sr = rb * 8 + rr;
            const float v0 = (c > 0)   ? __half2float(s[sr][c - 1]) : 0.f;
            const float v1 =             __half2float(s[sr][c]);
            const float v2 = (c < 127) ? __half2float(s[sr][c + 1]) : 0.f;
            const float d0 = w[0] * v0 + w[1] * v1 + w[2] * v2;
            const float d1 = w[3] * v0 + w[4] * v1 + w[5] * v2;
            const float d2 = w[6] * v0 + w[7] * v1 + w[8] * v2;
            if (rr < 8)             o[rr]     = d0;
            if (rr >= 1 && rr <= 8) o[rr - 1] += d1;
            if (rr >= 2)            o[rr - 2] += d2;
        }
#pragma unroll
        for (int y = 0; y < 8; y++)
            outp[(r0 + rb * 8 + y) * 128 + c] = __float2half_rn(o[y]);
    }
}

// ============================================================
// Partial Gram (48x48) + q/k norm partials; ns-split reduced in-warp.
// ============================================================
__global__ __launch_bounds__(256) void gram_kernel()
{
    const int chunk = blockIdx.x;
    const int bh    = blockIdx.y;
    const int b = bh >> 2, h = bh & 3;

    __shared__ float qs[48][132];
    __shared__ float ks[48][132];

    const __half* qbase = g_dwq + ((size_t)b * C3 + h * HC) * HW;
    const __half* kbase = qbase + (size_t)C_ * HW;

    const int tid = threadIdx.x;
    const int ns = tid & 3;
    const int td = (tid >> 2) & 7;
    const int tc = tid >> 5;

    float acc[6][6];
#pragma unroll
    for (int i = 0; i < 6; i++)
#pragma unroll
        for (int j = 0; j < 6; j++) acc[i][j] = 0.f;
    float nqa[6] = {0,0,0,0,0,0};
    float nka[6] = {0,0,0,0,0,0};

    for (int sub = 0; sub < 4; sub++) {
        const int n0 = (chunk * 4 + sub) * NCHUNK;
        const __half* qb = qbase + n0;
        const __half* kb = kbase + n0;

        __syncthreads();
        for (int i = tid; i < 48 * 16; i += 256) {
            const int r  = i >> 4;
            const int c8 = (i & 15) << 3;
            uint4 vq = *(const uint4*)&qb[(size_t)r * HW + c8];
            uint4 vk = *(const uint4*)&kb[(size_t)r * HW + c8];
            const __half2* hq = (const __half2*)&vq;
            const __half2* hk = (const __half2*)&vk;
#pragma unroll
            for (int j = 0; j < 4; j++) {
                float2 fq = __half22float2(hq[j]);
                float2 fk = __half22float2(hk[j]);
                qs[r][c8 + 2 * j]     = fq.x;
                qs[r][c8 + 2 * j + 1] = fq.y;
                ks[r][c8 + 2 * j]     = fk.x;
                ks[r][c8 + 2 * j + 1] = fk.y;
            }
        }
        __syncthreads();

        for (int nn = 0; nn < 32; nn += 4) {
            const int col = ns * 32 + ((nn + ns * 8) & 31);
            float4 qv[6], kv[6];
#pragma unroll
            for (int i = 0; i < 6; i++) {
                qv[i] = *(float4*)&qs[tc * 6 + i][col];
                kv[i] = *(float4*)&ks[td * 6 + i][col];
            }
#pragma unroll
            for (int i = 0; i < 6; i++)
#pragma unroll
                for (int j = 0; j < 6; j++)
                    acc[i][j] += qv[i].x * kv[j].x + qv[i].y * kv[j].y +
                                 qv[i].z * kv[j].z + qv[i].w * kv[j].w;
            if (td == 0) {
#pragma unroll
                for (int i = 0; i < 6; i++)
                    nqa[i] += qv[i].x * qv[i].x + qv[i].y * qv[i].y +
                              qv[i].z * qv[i].z + qv[i].w * qv[i].w;
            }
            if (tc == 0) {
#pragma unroll
                for (int j = 0; j < 6; j++)
                    nka[j] += kv[j].x * kv[j].x + kv[j].y * kv[j].y +
                              kv[j].z * kv[j].z + kv[j].w * kv[j].w;
            }
        }
    }

#pragma unroll
    for (int i = 0; i < 6; i++)
#pragma unroll
        for (int j = 0; j < 6; j++) {
            float v = acc[i][j];
            v += __shfl_xor_sync(0xffffffffu, v, 1);
            v += __shfl_xor_sync(0xffffffffu, v, 2);
            acc[i][j] = v;
        }
#pragma unroll
    for (int i = 0; i < 6; i++) {
        float v = nqa[i];
        v += __shfl_xor_sync(0xffffffffu, v, 1);
        v += __shfl_xor_sync(0xffffffffu, v, 2);
        nqa[i] = v;
        float u = nka[i];
        u += __shfl_xor_sync(0xffffffffu, u, 1);
        u += __shfl_xor_sync(0xffffffffu, u, 2);
        nka[i] = u;
    }

    if (ns == 0) {
        float* out = g_part + ((size_t)chunk * 32 + bh) * PART_STRIDE;
#pragma unroll
        for (int i = 0; i < 6; i++)
#pragma unroll
            for (int j = 0; j < 6; j++)
                out[(tc * 6 + i) * 48 + td * 6 + j] = acc[i][j];
        if (td == 0) {
#pragma unroll
            for (int i = 0; i < 6; i++) out[2304 + tc * 6 + i] = nqa[i];
        }
        if (tc == 0) {
#pragma unroll
            for (int j = 0; j < 6; j++) out[2352 + td * 6 + j] = nka[j];
        }
    }
}

__global__ __launch_bounds__(256) void reduce_kernel()
{
    const int idx = blockIdx.x * 256 + threadIdx.x;
    if (idx >= 32 * PART_STRIDE) return;
    const int bh = idx / PART_STRIDE;
    const int e  = idx % PART_STRIDE;
    const float* p = g_part + (size_t)bh * PART_STRIDE + e;
    float s = 0.f;
    for (int ch = 0; ch < NPART; ch++)
        s += p[(size_t)ch * 32 * PART_STRIDE];
    if (e < 2304)       g_gram[bh * 2304 + e]      = s;
    else if (e < 2352)  g_nq[bh * 48 + (e - 2304)] = s;
    else                g_nk[bh * 48 + (e - 2352)] = s;
}

// ============================================================
__global__ __launch_bounds__(32) void softmax_kernel(const float* __restrict__ temperature)
{
    const int row = blockIdx.x;
    const int bh = row / 48, c = row % 48;
    const int h = bh & 3;
    const int lane = threadIdx.x;

    const float* g = g_gram + (bh * 48 + c) * 48;
    const float t = temperature[h];
    const float qn = fmaxf(sqrtf(g_nq[bh * 48 + c]), 1e-12f);
    const float sq = t / qn;

    float v0 = g[lane] * sq / fmaxf(sqrtf(g_nk[bh * 48 + lane]), 1e-12f);
    float v1 = -3.4e38f;
    if (lane < 16)
        v1 = g[lane + 32] * sq / fmaxf(sqrtf(g_nk[bh * 48 + lane + 32]), 1e-12f);

    float m = fmaxf(v0, v1);
#pragma unroll
    for (int o = 16; o; o >>= 1) m = fmaxf(m, __shfl_xor_sync(0xffffffffu, m, o));
    const float e0 = expf(v0 - m);
    const float e1 = (lane < 16) ? expf(v1 - m) : 0.f;
    float s = e0 + e1;
#pragma unroll
    for (int o = 16; o; o >>= 1) s += __shfl_xor_sync(0xffffffffu, s, o);
    const float inv = 1.f / s;

    float* a = g_attn + (bh * 48 + c) * 48;
    a[lane] = e0 * inv;
    if (lane < 16) a[lane + 32] = e1 * inv;
}

// ============================================================
// Weff written DIRECTLY into the fragment-uint4 layout.
// ============================================================
__global__ __launch_bounds__(256) void weff_kernel(const float* __restrict__ wproj)
{
    const int idx = blockIdx.x * 256 + threadIdx.x;
    if (idx >= B_ * C_ * C_) return;
    const int b = idx / (C_ * C_);
    const int r = idx % (C_ * C_);
    const int o = r / C_;
    const int j = r % C_;
    const int h = j / HC, d = j % HC;

    const float* wp = wproj + o * C_ + h * HC;
    const float* at = g_attn + ((b * 4 + h) * 48) * 48 + d;
    float s = 0.f;
#pragma unroll 8
    for (int cc = 0; cc < 48; cc++)
        s += wp[cc] * at[cc * 48];

    const int mtile = o / 96;
    const int mloc  = o % 96;
    const int wmh   = mloc / 48;
    const int rr    = mloc % 48;
    const int mt    = rr / 16;
    const int s16   = rr % 16;
    const int colsel = s16 >> 3;
    const int grp    = s16 & 7;
    const int it     = j >> 4;
    const int jr     = (j >> 1) & 7;
    const int rowsel = jr >> 2;
    const int qd     = jr & 3;
    const int lane   = grp * 4 + qd;
    const int reg    = rowsel * 2 + colsel;

    const size_t u4 = (size_t)(b * 2 + mtile) * TILE_U4 +
                      ((it * 3 + mt) * 2 + wmh) * 32 + lane;
    ((__half*)g_weffh)[u4 * 8 + reg * 2 + (j & 1)] = __float2half_rn(s);
}

// ============================================================
extern "C" void kernel_launch(void* const* d_in, const int* in_sizes, int n_in,
                              void* d_out, int out_size)
{
    const float *x = nullptr, *w_qkv = nullptr, *w_dw = nullptr,
                *temperature = nullptr, *w_proj = nullptr;
    for (int i = 0; i < n_in; i++) {
        switch (in_sizes[i]) {
            case 25165824: x           = (const float*)d_in[i]; break;
            case 110592:   w_qkv       = (const float*)d_in[i]; break;
            case 5184:     w_dw        = (const float*)d_in[i]; break;
            case 4:        temperature = (const float*)d_in[i]; break;
            case 36864:    w_proj      = (const float*)d_in[i]; break;
        }
    }
    float* out = (float*)d_out;

    __half *qkv, *dwq;
    uint4 *wqkvh, *weffh;
    cudaGetSymbolAddress((void**)&qkv,   g_qkv);
    cudaGetSymbolAddress((void**)&dwq,   g_dwq);
    cudaGetSymbolAddress((void**)&wqkvh, g_wqkvh);
    cudaGetSymbolAddress((void**)&weffh, g_weffh);

    // keep ncu capture slot on the big GEMM (gemm1 = 4th launch)
    noop_kernel<<<1, 32>>>();
    noop_kernel<<<1, 32>>>();

    // 0) pack W_qkv -> fragment-uint4 layout
    pack_w_kernel<<<(6 * TILE_U4 + 255) / 256, 256>>>(w_qkv);

    // 1) qkv[b] = W_qkv @ x[b]  (256 threads, 16 warps/SM)
    gemm_f16<false, true><<<dim3(C3 / BM, HW / BN, B_), 256>>>(
        wqkvh, x, qkv, (size_t)0, (size_t)C_ * HW, (size_t)C3 * HW);

    // 2) depthwise 3x3 (fp16 smem tile)
    dwconv_kernel<<<dim3(2, C3, B_), 256>>>(w_dw);

    // 3) Gram + norm partials
    gram_kernel<<<dim3(GCHUNKS, 32), 256>>>();

    // 4) reduce partials
    reduce_kernel<<<(32 * PART_STRIDE + 255) / 256, 256>>>();

    // 5) scaled softmax
    softmax_kernel<<<32 * 48, 32>>>(temperature);

    // 6) Weff = W_proj @ attn, written packed
    weff_kernel<<<(B_ * C_ * C_ + 255) / 256, 256>>>(w_proj);

    // 7) out[b] = Weff[b] @ V[b]
    gemm_f16<true, false><<<dim3(C_ / BM, HW / BN, B_), 256>>>(
        weffh, dwq + (size_t)2 * C_ * HW, out,
        (size_t)(2 * TILE_U4), (size_t)C3 * HW, (size_t)C_ * HW);
}

// round 16
// speedup vs baseline: 1.1172x; 1.1172x over previous
#include <cuda_runtime.h>
#include <cuda_fp16.h>
#include <math.h>
#include <stdint.h>

#define B_      8
#define C_      192
#define C3      576
#define HW      16384
#define HEADS_  4
#define HC      48
#define NCHUNK  128
#define GCHUNKS 32
#define NPART   32
#define PART_STRIDE 2400
#define TILE_U4 2304   // uint4 per 96-row x 192-k packed A tile

// -------- device scratch --------
__device__ __half  g_qkv [(size_t)B_ * C3 * HW];
__device__ __half  g_dwq [(size_t)B_ * C3 * HW];
__device__ float   g_part[(size_t)NPART * 32 * PART_STRIDE];
__device__ float   g_gram[32 * HC * HC];
__device__ float   g_nq  [32 * HC];
__device__ float   g_nk  [32 * HC];
__device__ float   g_attn[32 * HC * HC];
__device__ uint4   g_wqkvh[6 * TILE_U4];
__device__ uint4   g_weffh[B_ * 2 * TILE_U4];

// ============================================================
__device__ __forceinline__ void mma_f16(float* d, const uint32_t* a,
                                        uint32_t b0, uint32_t b1) {
    asm volatile(
        "mma.sync.aligned.m16n8k16.row.col.f32.f16.f16.f32 "
        "{%0,%1,%2,%3}, {%4,%5,%6,%7}, {%8,%9}, {%0,%1,%2,%3};\n"
        : "+f"(d[0]), "+f"(d[1]), "+f"(d[2]), "+f"(d[3])
        : "r"(a[0]), "r"(a[1]), "r"(a[2]), "r"(a[3]),
          "r"(b0), "r"(b1));
}

__device__ __forceinline__ __half2 f2h2(float a, float b) {
    return __float22half2_rn(make_float2(a, b));
}

__device__ __forceinline__ uint32_t h2u(__half2 h) {
    union { __half2 h; uint32_t u; } c; c.h = h; return c.u;
}

// ============================================================
// Pack W_qkv (576x192 fp32) -> fragment-uint4 layout.
// ============================================================
__global__ __launch_bounds__(256) void pack_w_kernel(const float* __restrict__ w)
{
    const int idx = blockIdx.x * 256 + threadIdx.x;
    if (idx >= 6 * TILE_U4) return;
    const int mtile = idx / TILE_U4;
    const int rem   = idx % TILE_U4;
    const int lane  = rem & 31;
    int t = rem >> 5;
    const int wmh = t & 1;  t >>= 1;
    const int mt  = t % 3;
    const int it  = t / 3;
    const int grp = lane >> 2, qd = lane & 3;

    const int m   = mtile * 96 + wmh * 48 + mt * 16 + grp;
    const int k2a = it * 8 + qd;
    const int k2b = k2a + 4;

    uint4 o;
    o.x = h2u(f2h2(w[m * C_ + 2 * k2a],       w[m * C_ + 2 * k2a + 1]));
    o.y = h2u(f2h2(w[(m + 8) * C_ + 2 * k2a], w[(m + 8) * C_ + 2 * k2a + 1]));
    o.z = h2u(f2h2(w[m * C_ + 2 * k2b],       w[m * C_ + 2 * k2b + 1]));
    o.w = h2u(f2h2(w[(m + 8) * C_ + 2 * k2b], w[(m + 8) * C_ + 2 * k2b + 1]));
    g_wqkvh[idx] = o;
}

// ============================================================
// Tensor-core GEMM (round-14 winner): C = A_packed @ B[b](192xN), N=HW.
// BM=96 BN=128 BK=16. 128 threads / 4 warps (2M x 2N), warp tile 48x64.
// A: coalesced LDG.128 double-buffered 1 ahead.
// B: LDG issued 2 iterations ahead of its STS (distance-2 prefetch).
// ============================================================
#define BM 96
#define BN 128
#define BSX 136

template <bool B_HALF, bool OUT_HALF>
__global__ __launch_bounds__(128, 3) void gemm_f16(
    const uint4* __restrict__ Apk, const void* __restrict__ Bv,
    void* __restrict__ Cv, size_t sAb4, size_t sBb, size_t sCb)
{
    __shared__ __half2 Bsh[2][8][BSX];

    const int N = HW;
    const int n0 = blockIdx.y * BN;

    const int tid  = threadIdx.x;
    const int warp = tid >> 5;
    const int lane = tid & 31;
    const int wmh = warp & 1;
    const int wn  = (warp >> 1) * 64;
    const int grp = lane >> 2;
    const int qd  = lane & 3;

    const uint4* Ap = Apk + (size_t)blockIdx.z * sAb4 + (size_t)blockIdx.x * TILE_U4;

    const int bk2 = tid >> 4;            // 0..7
    const int bnc = (tid & 15) << 3;     // 0..120

    const float*  Bf = (const float*)Bv + (size_t)blockIdx.z * sBb;
    const __half* Bh = (const __half*)Bv + (size_t)blockIdx.z * sBb;

    float4 bRegF[4];
    uint4  bRegH[2];
    uint4  aBuf[2][3];

    auto loadG = [&](int k0) {
        if (B_HALF) {
            bRegH[0] = *(const uint4*)&Bh[(size_t)(k0 + 2 * bk2)     * N + n0 + bnc];
            bRegH[1] = *(const uint4*)&Bh[(size_t)(k0 + 2 * bk2 + 1) * N + n0 + bnc];
        } else {
            bRegF[0] = *(const float4*)&Bf[(size_t)(k0 + 2 * bk2)     * N + n0 + bnc];
            bRegF[1] = *(const float4*)&Bf[(size_t)(k0 + 2 * bk2)     * N + n0 + bnc + 4];
            bRegF[2] = *(const float4*)&Bf[(size_t)(k0 + 2 * bk2 + 1) * N + n0 + bnc];
            bRegF[3] = *(const float4*)&Bf[(size_t)(k0 + 2 * bk2 + 1) * N + n0 + bnc + 4];
        }
    };

    auto loadA = [&](int it, uint4* dst) {
#pragma unroll
        for (int mt = 0; mt < 3; mt++)
            dst[mt] = __ldg(&Ap[((it * 3 + mt) * 2 + wmh) * 32 + lane]);
    };

    auto storeS = [&](int buf) {
        __half2 h[8];
        if (B_HALF) {
            const __half* h0 = (const __half*)&bRegH[0];
            const __half* h1 = (const __half*)&bRegH[1];
#pragma unroll
            for (int j = 0; j < 8; j++) h[j] = __halves2half2(h0[j], h1[j]);
        } else {
            const float r0[8] = {bRegF[0].x, bRegF[0].y, bRegF[0].z, bRegF[0].w,
                                 bRegF[1].x, bRegF[1].y, bRegF[1].z, bRegF[1].w};
            const float r1[8] = {bRegF[2].x, bRegF[2].y, bRegF[2].z, bRegF[2].w,
                                 bRegF[3].x, bRegF[3].y, bRegF[3].z, bRegF[3].w};
#pragma unroll
            for (int j = 0; j < 8; j++) h[j] = f2h2(r0[j], r1[j]);
        }
        *(uint4*)&Bsh[buf][bk2][bnc]     = *(uint4*)&h[0];
        *(uint4*)&Bsh[buf][bk2][bnc + 4] = *(uint4*)&h[4];
    };

    float acc[3][8][4];
#pragma unroll
    for (int i = 0; i < 3; i++)
#pragma unroll
        for (int j = 0; j < 8; j++)
#pragma unroll
            for (int r = 0; r < 4; r++) acc[i][j][r] = 0.f;

    loadG(0);
    storeS(0);
    loadA(0, aBuf[0]);
    loadG(16);
    __syncthreads();

#pragma unroll 2
    for (int it = 0; it < 12; it++) {
        const int cur = it & 1;
        const int nxt = cur ^ 1;
        if (it + 1 < 12) loadA(it + 1, aBuf[nxt]);

#pragma unroll
        for (int nt = 0; nt < 8; nt++) {
            const int n = wn + nt * 8 + grp;
            const uint32_t b0 = *(const uint32_t*)&Bsh[cur][qd    ][n];
            const uint32_t b1 = *(const uint32_t*)&Bsh[cur][qd + 4][n];
#pragma unroll
            for (int mt = 0; mt < 3; mt++)
                mma_f16(acc[mt][nt], (const uint32_t*)&aBuf[cur][mt], b0, b1);
        }

        if (it + 1 < 12) {
            storeS(nxt);
            if (it + 2 < 12) loadG((it + 2) * 16);
            __syncthreads();
        }
    }

    const int m0 = blockIdx.x * BM;
    const int wm = wmh * 48;
    if (OUT_HALF) {
        __half* Ch = (__half*)Cv + (size_t)blockIdx.z * sCb;
#pragma unroll
        for (int mt = 0; mt < 3; mt++) {
#pragma unroll
            for (int nt = 0; nt < 8; nt++) {
                const int row = m0 + wm + mt * 16 + grp;
                const int col = n0 + wn + nt * 8 + qd * 2;
                *(__half2*)&Ch[(size_t)row * N + col] =
                    f2h2(acc[mt][nt][0], acc[mt][nt][1]);
                *(__half2*)&Ch[(size_t)(row + 8) * N + col] =
                    f2h2(acc[mt][nt][2], acc[mt][nt][3]);
            }
        }
    } else {
        float* Cf = (float*)Cv + (size_t)blockIdx.z * sCb;
#pragma unroll
        for (int mt = 0; mt < 3; mt++) {
#pragma unroll
            for (int nt = 0; nt < 8; nt++) {
                const int row = m0 + wm + mt * 16 + grp;
                const int col = n0 + wn + nt * 8 + qd * 2;
                *(float2*)&Cf[(size_t)row * N + col]       = make_float2(acc[mt][nt][0], acc[mt][nt][1]);
                *(float2*)&Cf[(size_t)(row + 8) * N + col] = make_float2(acc[mt][nt][2], acc[mt][nt][3]);
            }
        }
    }
}

// ============================================================
__global__ void noop_kernel() {}

// ============================================================
// Depthwise 3x3 SAME, fp16 smem tile (66x136 halves), fp32 compute.
// ============================================================
__global__ __launch_bounds__(256) void dwconv_kernel(const float* __restrict__ wdw)
{
    __shared__ __half s[66][136];

    const int half_ = blockIdx.x;
    const int ch    = blockIdx.y;
    const int b     = blockIdx.z;
    const int r0    = half_ * 64;

    const __half* in = g_qkv + ((size_t)b * C3 + ch) * HW;
    __half* outp = g_dwq + ((size_t)b * C3 + ch) * HW;
    const int tid = threadIdx.x;

    const uint4 z4 = make_uint4(0, 0, 0, 0);
    for (int i = tid; i < 66 * 16; i += 256) {
        const int sr = i >> 4;
        const int c8 = (i & 15) << 3;
        const int gr = r0 - 1 + sr;
        uint4 v = (gr >= 0 && gr < 128) ? *(const uint4*)&in[gr * 128 + c8] : z4;
        *(uint4*)&s[sr][c8] = v;
    }
    __syncthreads();

    float w[9];
#pragma unroll
    for (int i = 0; i < 9; i++) w[i] = __ldg(&wdw[ch * 9 + i]);

    const int lane = tid & 31;
    const int rb   = tid >> 5;

#pragma unroll
    for (int seg = 0; seg < 4; seg++) {
        const int c = lane + seg * 32;
        float o[8];
#pragma unroll
        for (int rr = 0; rr < 10; rr++) {
            const int sr = rb * 8 + rr;
            const float v0 = (c > 0)   ? __half2float(s[sr][c - 1]) : 0.f;
            const float v1 =             __half2float(s[sr][c]);
            const float v2 = (c < 127) ? __half2float(s[sr][c + 1]) : 0.f;
            const float d0 = w[0] * v0 + w[1] * v1 + w[2] * v2;
            const float d1 = w[3] * v0 + w[4] * v1 + w[5] * v2;
            const float d2 = w[6] * v0 + w[7] * v1 + w[8] * v2;
            if (rr < 8)             o[rr]     = d0;
            if (rr >= 1 && rr <= 8) o[rr - 1] += d1;
            if (rr >= 2)            o[rr - 2] += d2;
        }
#pragma unroll
        for (int y = 0; y < 8; y++)
            outp[(r0 + rb * 8 + y) * 128 + c] = __float2half_rn(o[y]);
    }
}

// ============================================================
// Partial Gram (48x48) + q/k norm partials; ns-split reduced in-warp.
// ============================================================
__global__ __launch_bounds__(256) void gram_kernel()
{
    const int chunk = blockIdx.x;
    const int bh    = blockIdx.y;
    const int b = bh >> 2, h = bh & 3;

    __shared__ float qs[48][132];
    __shared__ float ks[48][132];

    const __half* qbase = g_dwq + ((size_t)b * C3 + h * HC) * HW;
    const __half* kbase = qbase + (size_t)C_ * HW;

    const int tid = threadIdx.x;
    const int ns = tid & 3;
    const int td = (tid >> 2) & 7;
    const int tc = tid >> 5;

    float acc[6][6];
#pragma unroll
    for (int i = 0; i < 6; i++)
#pragma unroll
        for (int j = 0; j < 6; j++) acc[i][j] = 0.f;
    float nqa[6] = {0,0,0,0,0,0};
    float nka[6] = {0,0,0,0,0,0};

    for (int sub = 0; sub < 4; sub++) {
        const int n0 = (chunk * 4 + sub) * NCHUNK;
        const __half* qb = qbase + n0;
        const __half* kb = kbase + n0;

        __syncthreads();
        for (int i = tid; i < 48 * 16; i += 256) {
            const int r  = i >> 4;
            const int c8 = (i & 15) << 3;
            uint4 vq = *(const uint4*)&qb[(size_t)r * HW + c8];
            uint4 vk = *(const uint4*)&kb[(size_t)r * HW + c8];
            const __half2* hq = (const __half2*)&vq;
            const __half2* hk = (const __half2*)&vk;
#pragma unroll
            for (int j = 0; j < 4; j++) {
                float2 fq = __half22float2(hq[j]);
                float2 fk = __half22float2(hk[j]);
                qs[r][c8 + 2 * j]     = fq.x;
                qs[r][c8 + 2 * j + 1] = fq.y;
                ks[r][c8 + 2 * j]     = fk.x;
                ks[r][c8 + 2 * j + 1] = fk.y;
            }
        }
        __syncthreads();

        for (int nn = 0; nn < 32; nn += 4) {
            const int col = ns * 32 + ((nn + ns * 8) & 31);
            float4 qv[6], kv[6];
#pragma unroll
            for (int i = 0; i < 6; i++) {
                qv[i] = *(float4*)&qs[tc * 6 + i][col];
                kv[i] = *(float4*)&ks[td * 6 + i][col];
            }
#pragma unroll
            for (int i = 0; i < 6; i++)
#pragma unroll
                for (int j = 0; j < 6; j++)
                    acc[i][j] += qv[i].x * kv[j].x + qv[i].y * kv[j].y +
                                 qv[i].z * kv[j].z + qv[i].w * kv[j].w;
            if (td == 0) {
#pragma unroll
                for (int i = 0; i < 6; i++)
                    nqa[i] += qv[i].x * qv[i].x + qv[i].y * qv[i].y +
                              qv[i].z * qv[i].z + qv[i].w * qv[i].w;
            }
            if (tc == 0) {
#pragma unroll
                for (int j = 0; j < 6; j++)
                    nka[j] += kv[j].x * kv[j].x + kv[j].y * kv[j].y +
                              kv[j].z * kv[j].z + kv[j].w * kv[j].w;
            }
        }
    }

#pragma unroll
    for (int i = 0; i < 6; i++)
#pragma unroll
        for (int j = 0; j < 6; j++) {
            float v = acc[i][j];
            v += __shfl_xor_sync(0xffffffffu, v, 1);
            v += __shfl_xor_sync(0xffffffffu, v, 2);
            acc[i][j] = v;
        }
#pragma unroll
    for (int i = 0; i < 6; i++) {
        float v = nqa[i];
        v += __shfl_xor_sync(0xffffffffu, v, 1);
        v += __shfl_xor_sync(0xffffffffu, v, 2);
        nqa[i] = v;
        float u = nka[i];
        u += __shfl_xor_sync(0xffffffffu, u, 1);
        u += __shfl_xor_sync(0xffffffffu, u, 2);
        nka[i] = u;
    }

    if (ns == 0) {
        float* out = g_part + ((size_t)chunk * 32 + bh) * PART_STRIDE;
#pragma unroll
        for (int i = 0; i < 6; i++)
#pragma unroll
            for (int j = 0; j < 6; j++)
                out[(tc * 6 + i) * 48 + td * 6 + j] = acc[i][j];
        if (td == 0) {
#pragma unroll
            for (int i = 0; i < 6; i++) out[2304 + tc * 6 + i] = nqa[i];
        }
        if (tc == 0) {
#pragma unroll
            for (int j = 0; j < 6; j++) out[2352 + td * 6 + j] = nka[j];
        }
    }
}

__global__ __launch_bounds__(256) void reduce_kernel()
{
    const int idx = blockIdx.x * 256 + threadIdx.x;
    if (idx >= 32 * PART_STRIDE) return;
    const int bh = idx / PART_STRIDE;
    const int e  = idx % PART_STRIDE;
    const float* p = g_part + (size_t)bh * PART_STRIDE + e;
    float s = 0.f;
    for (int ch = 0; ch < NPART; ch++)
        s += p[(size_t)ch * 32 * PART_STRIDE];
    if (e < 2304)       g_gram[bh * 2304 + e]      = s;
    else if (e < 2352)  g_nq[bh * 48 + (e - 2304)] = s;
    else                g_nk[bh * 48 + (e - 2352)] = s;
}

// ============================================================
__global__ __launch_bounds__(32) void softmax_kernel(const float* __restrict__ temperature)
{
    const int row = blockIdx.x;
    const int bh = row / 48, c = row % 48;
    const int h = bh & 3;
    const int lane = threadIdx.x;

    const float* g = g_gram + (bh * 48 + c) * 48;
    const float t = temperature[h];
    const float qn = fmaxf(sqrtf(g_nq[bh * 48 + c]), 1e-12f);
    const float sq = t / qn;

    float v0 = g[lane] * sq / fmaxf(sqrtf(g_nk[bh * 48 + lane]), 1e-12f);
    float v1 = -3.4e38f;
    if (lane < 16)
        v1 = g[lane + 32] * sq / fmaxf(sqrtf(g_nk[bh * 48 + lane + 32]), 1e-12f);

    float m = fmaxf(v0, v1);
#pragma unroll
    for (int o = 16; o; o >>= 1) m = fmaxf(m, __shfl_xor_sync(0xffffffffu, m, o));
    const float e0 = expf(v0 - m);
    const float e1 = (lane < 16) ? expf(v1 - m) : 0.f;
    float s = e0 + e1;
#pragma unroll
    for (int o = 16; o; o >>= 1) s += __shfl_xor_sync(0xffffffffu, s, o);
    const float inv = 1.f / s;

    float* a = g_attn + (bh * 48 + c) * 48;
    a[lane] = e0 * inv;
    if (lane < 16) a[lane + 32] = e1 * inv;
}

// ============================================================
// Weff written DIRECTLY into the fragment-uint4 layout.
// ============================================================
__global__ __launch_bounds__(256) void weff_kernel(const float* __restrict__ wproj)
{
    const int idx = blockIdx.x * 256 + threadIdx.x;
    if (idx >= B_ * C_ * C_) return;
    const int b = idx / (C_ * C_);
    const int r = idx % (C_ * C_);
    const int o = r / C_;
    const int j = r % C_;
    const int h = j / HC, d = j % HC;

    const float* wp = wproj + o * C_ + h * HC;
    const float* at = g_attn + ((b * 4 + h) * 48) * 48 + d;
    float s = 0.f;
#pragma unroll 8
    for (int cc = 0; cc < 48; cc++)
        s += wp[cc] * at[cc * 48];

    const int mtile = o / 96;
    const int mloc  = o % 96;
    const int wmh   = mloc / 48;
    const int rr    = mloc % 48;
    const int mt    = rr / 16;
    const int s16   = rr % 16;
    const int colsel = s16 >> 3;
    const int grp    = s16 & 7;
    const int it     = j >> 4;
    const int jr     = (j >> 1) & 7;
    const int rowsel = jr >> 2;
    const int qd     = jr & 3;
    const int lane   = grp * 4 + qd;
    const int reg    = rowsel * 2 + colsel;

    const size_t u4 = (size_t)(b * 2 + mtile) * TILE_U4 +
                      ((it * 3 + mt) * 2 + wmh) * 32 + lane;
    ((__half*)g_weffh)[u4 * 8 + reg * 2 + (j & 1)] = __float2half_rn(s);
}

// ============================================================
extern "C" void kernel_launch(void* const* d_in, const int* in_sizes, int n_in,
                              void* d_out, int out_size)
{
    const float *x = nullptr, *w_qkv = nullptr, *w_dw = nullptr,
                *temperature = nullptr, *w_proj = nullptr;
    for (int i = 0; i < n_in; i++) {
        switch (in_sizes[i]) {
            case 25165824: x           = (const float*)d_in[i]; break;
            case 110592:   w_qkv       = (const float*)d_in[i]; break;
            case 5184:     w_dw        = (const float*)d_in[i]; break;
            case 4:        temperature = (const float*)d_in[i]; break;
            case 36864:    w_proj      = (const float*)d_in[i]; break;
        }
    }
    float* out = (float*)d_out;

    __half *qkv, *dwq;
    uint4 *wqkvh, *weffh;
    cudaGetSymbolAddress((void**)&qkv,   g_qkv);
    cudaGetSymbolAddress((void**)&dwq,   g_dwq);
    cudaGetSymbolAddress((void**)&wqkvh, g_wqkvh);
    cudaGetSymbolAddress((void**)&weffh, g_weffh);

    // capture slot = 4th launch -> dwconv this round
    noop_kernel<<<1, 32>>>();

    // 0) pack W_qkv -> fragment-uint4 layout
    pack_w_kernel<<<(6 * TILE_U4 + 255) / 256, 256>>>(w_qkv);

    // 1) qkv[b] = W_qkv @ x[b]  (round-14 GEMM: 128 thr, distance-2 B)
    gemm_f16<false, true><<<dim3(C3 / BM, HW / BN, B_), 128>>>(
        wqkvh, x, qkv, (size_t)0, (size_t)C_ * HW, (size_t)C3 * HW);

    // 2) depthwise 3x3 (4th launch -> profiled this round)
    dwconv_kernel<<<dim3(2, C3, B_), 256>>>(w_dw);

    // 3) Gram + norm partials
    gram_kernel<<<dim3(GCHUNKS, 32), 256>>>();

    // 4) reduce partials
    reduce_kernel<<<(32 * PART_STRIDE + 255) / 256, 256>>>();

    // 5) scaled softmax
    softmax_kernel<<<32 * 48, 32>>>(temperature);

    // 6) Weff = W_proj @ attn, written packed
    weff_kernel<<<(B_ * C_ * C_ + 255) / 256, 256>>>(w_proj);

    // 7) out[b] = Weff[b] @ V[b]
    gemm_f16<true, false><<<dim3(C_ / BM, HW / BN, B_), 128>>>(
        weffh, dwq + (size_t)2 * C_ * HW, out,
        (size_t)(2 * TILE_U4), (size_t)C3 * HW, (size_t)C_ * HW);
}

// round 17
// speedup vs baseline: 1.4103x; 1.2623x over previous
#include <cuda_runtime.h>
#include <cuda_fp16.h>
#include <math.h>
#include <stdint.h>

#define B_      8
#define C_      192
#define C3      576
#define HW      16384
#define HEADS_  4
#define HC      48
#define NCH     16             // gram chunks; each block covers 8 subs x 128 px
#define NPART   64             // gram partial slots = NCH * 4 warps
#define PART_STRIDE 2400       // 2304 gram + 48 nq + 48 nk
#define TILE_U4 2304           // uint4 per 96-row x 192-k packed A tile

// -------- device scratch --------
__device__ __half  g_qkv [(size_t)B_ * C3 * HW];
__device__ __half  g_dwq [(size_t)B_ * C3 * HW];
__device__ float   g_part[(size_t)NPART * 32 * PART_STRIDE];
__device__ float   g_gram[32 * HC * HC];
__device__ float   g_nq  [32 * HC];
__device__ float   g_nk  [32 * HC];
__device__ float   g_attn[32 * HC * HC];
__device__ uint4   g_wqkvh[6 * TILE_U4];
__device__ uint4   g_weffh[B_ * 2 * TILE_U4];

// ============================================================
__device__ __forceinline__ void mma_f16(float* d, const uint32_t* a,
                                        uint32_t b0, uint32_t b1) {
    asm volatile(
        "mma.sync.aligned.m16n8k16.row.col.f32.f16.f16.f32 "
        "{%0,%1,%2,%3}, {%4,%5,%6,%7}, {%8,%9}, {%0,%1,%2,%3};\n"
        : "+f"(d[0]), "+f"(d[1]), "+f"(d[2]), "+f"(d[3])
        : "r"(a[0]), "r"(a[1]), "r"(a[2]), "r"(a[3]),
          "r"(b0), "r"(b1));
}

__device__ __forceinline__ __half2 f2h2(float a, float b) {
    return __float22half2_rn(make_float2(a, b));
}

__device__ __forceinline__ uint32_t h2u(__half2 h) {
    union { __half2 h; uint32_t u; } c; c.h = h; return c.u;
}

// ============================================================
// Pack W_qkv (576x192 fp32) -> fragment-uint4 layout.
// ============================================================
__global__ __launch_bounds__(256) void pack_w_kernel(const float* __restrict__ w)
{
    const int idx = blockIdx.x * 256 + threadIdx.x;
    if (idx >= 6 * TILE_U4) return;
    const int mtile = idx / TILE_U4;
    const int rem   = idx % TILE_U4;
    const int lane  = rem & 31;
    int t = rem >> 5;
    const int wmh = t & 1;  t >>= 1;
    const int mt  = t % 3;
    const int it  = t / 3;
    const int grp = lane >> 2, qd = lane & 3;

    const int m   = mtile * 96 + wmh * 48 + mt * 16 + grp;
    const int k2a = it * 8 + qd;
    const int k2b = k2a + 4;

    uint4 o;
    o.x = h2u(f2h2(w[m * C_ + 2 * k2a],       w[m * C_ + 2 * k2a + 1]));
    o.y = h2u(f2h2(w[(m + 8) * C_ + 2 * k2a], w[(m + 8) * C_ + 2 * k2a + 1]));
    o.z = h2u(f2h2(w[m * C_ + 2 * k2b],       w[m * C_ + 2 * k2b + 1]));
    o.w = h2u(f2h2(w[(m + 8) * C_ + 2 * k2b], w[(m + 8) * C_ + 2 * k2b + 1]));
    g_wqkvh[idx] = o;
}

// ============================================================
// Tensor-core GEMM (round-14 winner): C = A_packed @ B[b](192xN), N=HW.
// ============================================================
#define BM 96
#define BN 128
#define BSX 136

template <bool B_HALF, bool OUT_HALF>
__global__ __launch_bounds__(128, 3) void gemm_f16(
    const uint4* __restrict__ Apk, const void* __restrict__ Bv,
    void* __restrict__ Cv, size_t sAb4, size_t sBb, size_t sCb)
{
    __shared__ __half2 Bsh[2][8][BSX];

    const int N = HW;
    const int n0 = blockIdx.y * BN;

    const int tid  = threadIdx.x;
    const int warp = tid >> 5;
    const int lane = tid & 31;
    const int wmh = warp & 1;
    const int wn  = (warp >> 1) * 64;
    const int grp = lane >> 2;
    const int qd  = lane & 3;

    const uint4* Ap = Apk + (size_t)blockIdx.z * sAb4 + (size_t)blockIdx.x * TILE_U4;

    const int bk2 = tid >> 4;
    const int bnc = (tid & 15) << 3;

    const float*  Bf = (const float*)Bv + (size_t)blockIdx.z * sBb;
    const __half* Bh = (const __half*)Bv + (size_t)blockIdx.z * sBb;

    float4 bRegF[4];
    uint4  bRegH[2];
    uint4  aBuf[2][3];

    auto loadG = [&](int k0) {
        if (B_HALF) {
            bRegH[0] = *(const uint4*)&Bh[(size_t)(k0 + 2 * bk2)     * N + n0 + bnc];
            bRegH[1] = *(const uint4*)&Bh[(size_t)(k0 + 2 * bk2 + 1) * N + n0 + bnc];
        } else {
            bRegF[0] = *(const float4*)&Bf[(size_t)(k0 + 2 * bk2)     * N + n0 + bnc];
            bRegF[1] = *(const float4*)&Bf[(size_t)(k0 + 2 * bk2)     * N + n0 + bnc + 4];
            bRegF[2] = *(const float4*)&Bf[(size_t)(k0 + 2 * bk2 + 1) * N + n0 + bnc];
            bRegF[3] = *(const float4*)&Bf[(size_t)(k0 + 2 * bk2 + 1) * N + n0 + bnc + 4];
        }
    };

    auto loadA = [&](int it, uint4* dst) {
#pragma unroll
        for (int mt = 0; mt < 3; mt++)
            dst[mt] = __ldg(&Ap[((it * 3 + mt) * 2 + wmh) * 32 + lane]);
    };

    auto storeS = [&](int buf) {
        __half2 h[8];
        if (B_HALF) {
            const __half* h0 = (const __half*)&bRegH[0];
            const __half* h1 = (const __half*)&bRegH[1];
#pragma unroll
            for (int j = 0; j < 8; j++) h[j] = __halves2half2(h0[j], h1[j]);
        } else {
            const float r0[8] = {bRegF[0].x, bRegF[0].y, bRegF[0].z, bRegF[0].w,
                                 bRegF[1].x, bRegF[1].y, bRegF[1].z, bRegF[1].w};
            const float r1[8] = {bRegF[2].x, bRegF[2].y, bRegF[2].z, bRegF[2].w,
                                 bRegF[3].x, bRegF[3].y, bRegF[3].z, bRegF[3].w};
#pragma unroll
            for (int j = 0; j < 8; j++) h[j] = f2h2(r0[j], r1[j]);
        }
        *(uint4*)&Bsh[buf][bk2][bnc]     = *(uint4*)&h[0];
        *(uint4*)&Bsh[buf][bk2][bnc + 4] = *(uint4*)&h[4];
    };

    float acc[3][8][4];
#pragma unroll
    for (int i = 0; i < 3; i++)
#pragma unroll
        for (int j = 0; j < 8; j++)
#pragma unroll
            for (int r = 0; r < 4; r++) acc[i][j][r] = 0.f;

    loadG(0);
    storeS(0);
    loadA(0, aBuf[0]);
    loadG(16);
    __syncthreads();

#pragma unroll 2
    for (int it = 0; it < 12; it++) {
        const int cur = it & 1;
        const int nxt = cur ^ 1;
        if (it + 1 < 12) loadA(it + 1, aBuf[nxt]);

#pragma unroll
        for (int nt = 0; nt < 8; nt++) {
            const int n = wn + nt * 8 + grp;
            const uint32_t b0 = *(const uint32_t*)&Bsh[cur][qd    ][n];
            const uint32_t b1 = *(const uint32_t*)&Bsh[cur][qd + 4][n];
#pragma unroll
            for (int mt = 0; mt < 3; mt++)
                mma_f16(acc[mt][nt], (const uint32_t*)&aBuf[cur][mt], b0, b1);
        }

        if (it + 1 < 12) {
            storeS(nxt);
            if (it + 2 < 12) loadG((it + 2) * 16);
            __syncthreads();
        }
    }

    const int m0 = blockIdx.x * BM;
    const int wm = wmh * 48;
    if (OUT_HALF) {
        __half* Ch = (__half*)Cv + (size_t)blockIdx.z * sCb;
#pragma unroll
        for (int mt = 0; mt < 3; mt++) {
#pragma unroll
            for (int nt = 0; nt < 8; nt++) {
                const int row = m0 + wm + mt * 16 + grp;
                const int col = n0 + wn + nt * 8 + qd * 2;
                *(__half2*)&Ch[(size_t)row * N + col] =
                    f2h2(acc[mt][nt][0], acc[mt][nt][1]);
                *(__half2*)&Ch[(size_t)(row + 8) * N + col] =
                    f2h2(acc[mt][nt][2], acc[mt][nt][3]);
            }
        }
    } else {
        float* Cf = (float*)Cv + (size_t)blockIdx.z * sCb;
#pragma unroll
        for (int mt = 0; mt < 3; mt++) {
#pragma unroll
            for (int nt = 0; nt < 8; nt++) {
                const int row = m0 + wm + mt * 16 + grp;
                const int col = n0 + wn + nt * 8 + qd * 2;
                *(float2*)&Cf[(size_t)row * N + col]       = make_float2(acc[mt][nt][0], acc[mt][nt][1]);
                *(float2*)&Cf[(size_t)(row + 8) * N + col] = make_float2(acc[mt][nt][2], acc[mt][nt][3]);
            }
        }
    }
}

// ============================================================
// Depthwise 3x3 SAME, fp16 smem tile, fp32 compute.
// ============================================================
__global__ __launch_bounds__(256) void dwconv_kernel(const float* __restrict__ wdw)
{
    __shared__ __half s[66][136];

    const int half_ = blockIdx.x;
    const int ch    = blockIdx.y;
    const int b     = blockIdx.z;
    const int r0    = half_ * 64;

    const __half* in = g_qkv + ((size_t)b * C3 + ch) * HW;
    __half* outp = g_dwq + ((size_t)b * C3 + ch) * HW;
    const int tid = threadIdx.x;

    const uint4 z4 = make_uint4(0, 0, 0, 0);
    for (int i = tid; i < 66 * 16; i += 256) {
        const int sr = i >> 4;
        const int c8 = (i & 15) << 3;
        const int gr = r0 - 1 + sr;
        uint4 v = (gr >= 0 && gr < 128) ? *(const uint4*)&in[gr * 128 + c8] : z4;
        *(uint4*)&s[sr][c8] = v;
    }
    __syncthreads();

    float w[9];
#pragma unroll
    for (int i = 0; i < 9; i++) w[i] = __ldg(&wdw[ch * 9 + i]);

    const int lane = tid & 31;
    const int rb   = tid >> 5;

#pragma unroll
    for (int seg = 0; seg < 4; seg++) {
        const int c = lane + seg * 32;
        float o[8];
#pragma unroll
        for (int rr = 0; rr < 10; rr++) {
            const int sr = rb * 8 + rr;
            const float v0 = (c > 0)   ? __half2float(s[sr][c - 1]) : 0.f;
            const float v1 =             __half2float(s[sr][c]);
            const float v2 = (c < 127) ? __half2float(s[sr][c + 1]) : 0.f;
            const float d0 = w[0] * v0 + w[1] * v1 + w[2] * v2;
            const float d1 = w[3] * v0 + w[4] * v1 + w[5] * v2;
            const float d2 = w[6] * v0 + w[7] * v1 + w[8] * v2;
            if (rr < 8)             o[rr]     = d0;
            if (rr >= 1 && rr <= 8) o[rr - 1] += d1;
            if (rr >= 2)            o[rr - 2] += d2;
        }
#pragma unroll
        for (int y = 0; y < 8; y++)
            outp[(r0 + rb * 8 + y) * 128 + c] = __float2half_rn(o[y]);
    }
}

// ============================================================
// Tensor-core Gram: G[c][d] = sum_n q[c][n]*k[d][n] per (b,h).
// grid (16, 32), 128 threads / 4 warps. Each block: 8 subs x 128 px.
// smem tiles [row][68] half2 (stride 68 -> conflict-free frag LDS).
// Per warp: 2 k16 steps/sub, full 48x48 accumulated in regs.
// Norms from the same smem tiles (threads 0..95).
// ============================================================
__global__ __launch_bounds__(128) void gram_kernel()
{
    const int chunk = blockIdx.x;   // 0..15
    const int bh    = blockIdx.y;   // 0..31
    const int b = bh >> 2, h = bh & 3;

    __shared__ __half2 qs2[48][68];
    __shared__ __half2 ks2[48][68];

    const __half* qbase = g_dwq + ((size_t)b * C3 + h * HC) * HW;
    const __half* kbase = qbase + (size_t)C_ * HW;

    const int tid  = threadIdx.x;
    const int warp = tid >> 5;
    const int lane = tid & 31;
    const int grp  = lane >> 2;
    const int qd   = lane & 3;

    float acc[3][6][4];
#pragma unroll
    for (int i = 0; i < 3; i++)
#pragma unroll
        for (int j = 0; j < 6; j++)
#pragma unroll
            for (int r = 0; r < 4; r++) acc[i][j][r] = 0.f;
    float nrm = 0.f;
    const int nr = (tid < 48) ? tid : (tid - 48);

    for (int sub = 0; sub < 8; sub++) {
        const int n0 = (chunk * 8 + sub) * 128;
        __syncthreads();
        for (int i = tid; i < 48 * 16; i += 128) {
            const int r  = i >> 4;
            const int cg = i & 15;
            uint4 vq = *(const uint4*)&qbase[(size_t)r * HW + n0 + cg * 8];
            uint4 vk = *(const uint4*)&kbase[(size_t)r * HW + n0 + cg * 8];
            *(uint4*)&qs2[r][cg * 4] = vq;
            *(uint4*)&ks2[r][cg * 4] = vk;
        }
        __syncthreads();

#pragma unroll
        for (int st = 0; st < 2; st++) {
            const int k2b = (warp * 2 + st) * 8;
            uint32_t af[3][4];
#pragma unroll
            for (int mt = 0; mt < 3; mt++) {
                const int m = mt * 16 + grp;
                af[mt][0] = *(const uint32_t*)&qs2[m    ][k2b + qd];
                af[mt][1] = *(const uint32_t*)&qs2[m + 8][k2b + qd];
                af[mt][2] = *(const uint32_t*)&qs2[m    ][k2b + qd + 4];
                af[mt][3] = *(const uint32_t*)&qs2[m + 8][k2b + qd + 4];
            }
#pragma unroll
            for (int nt = 0; nt < 6; nt++) {
                const int n = nt * 8 + grp;
                const uint32_t b0 = *(const uint32_t*)&ks2[n][k2b + qd];
                const uint32_t b1 = *(const uint32_t*)&ks2[n][k2b + qd + 4];
#pragma unroll
                for (int mt = 0; mt < 3; mt++)
                    mma_f16(acc[mt][nt], af[mt], b0, b1);
            }
        }

        if (tid < 96) {
            const __half2* src = (tid < 48) ? &qs2[nr][0] : &ks2[nr][0];
            float s = 0.f;
#pragma unroll 16
            for (int k2 = 0; k2 < 64; k2++) {
                float2 f = __half22float2(src[k2]);
                s += f.x * f.x + f.y * f.y;
            }
            nrm += s;
        }
    }

    // per-warp gram partial (slot = chunk*4 + warp)
    float* outg = g_part + ((size_t)(chunk * 4 + warp) * 32 + bh) * PART_STRIDE;
#pragma unroll
    for (int mt = 0; mt < 3; mt++)
#pragma unroll
        for (int nt = 0; nt < 6; nt++) {
            const int row = mt * 16 + grp;
            const int col = nt * 8 + qd * 2;
            outg[row * 48 + col]           = acc[mt][nt][0];
            outg[row * 48 + col + 1]       = acc[mt][nt][1];
            outg[(row + 8) * 48 + col]     = acc[mt][nt][2];
            outg[(row + 8) * 48 + col + 1] = acc[mt][nt][3];
        }
    // norm partials (slot = chunk*4, offset 2304; threads own disjoint rows)
    if (tid < 96) {
        float* outn = g_part + ((size_t)(chunk * 4) * 32 + bh) * PART_STRIDE + 2304;
        outn[tid] = nrm;
    }
}

__global__ __launch_bounds__(256) void reduce_kernel()
{
    const int idx = blockIdx.x * 256 + threadIdx.x;
    if (idx >= 32 * PART_STRIDE) return;
    const int bh = idx / PART_STRIDE;
    const int e  = idx % PART_STRIDE;
    float s = 0.f;
    if (e < 2304) {
        const float* p = g_part + (size_t)bh * PART_STRIDE + e;
        for (int sl = 0; sl < NPART; sl++)
            s += p[(size_t)sl * 32 * PART_STRIDE];
        g_gram[bh * 2304 + e] = s;
    } else {
        const float* p = g_part + (size_t)bh * PART_STRIDE + e;
        for (int c = 0; c < NCH; c++)
            s += p[(size_t)(c * 4) * 32 * PART_STRIDE];
        const int e2 = e - 2304;
        if (e2 < 48) g_nq[bh * 48 + e2] = s;
        else         g_nk[bh * 48 + (e2 - 48)] = s;
    }
}

// ============================================================
__global__ __launch_bounds__(32) void softmax_kernel(const float* __restrict__ temperature)
{
    const int row = blockIdx.x;
    const int bh = row / 48, c = row % 48;
    const int h = bh & 3;
    const int lane = threadIdx.x;

    const float* g = g_gram + (bh * 48 + c) * 48;
    const float t = temperature[h];
    const float qn = fmaxf(sqrtf(g_nq[bh * 48 + c]), 1e-12f);
    const float sq = t / qn;

    float v0 = g[lane] * sq / fmaxf(sqrtf(g_nk[bh * 48 + lane]), 1e-12f);
    float v1 = -3.4e38f;
    if (lane < 16)
        v1 = g[lane + 32] * sq / fmaxf(sqrtf(g_nk[bh * 48 + lane + 32]), 1e-12f);

    float m = fmaxf(v0, v1);
#pragma unroll
    for (int o = 16; o; o >>= 1) m = fmaxf(m, __shfl_xor_sync(0xffffffffu, m, o));
    const float e0 = expf(v0 - m);
    const float e1 = (lane < 16) ? expf(v1 - m) : 0.f;
    float s = e0 + e1;
#pragma unroll
    for (int o = 16; o; o >>= 1) s += __shfl_xor_sync(0xffffffffu, s, o);
    const float inv = 1.f / s;

    float* a = g_attn + (bh * 48 + c) * 48;
    a[lane] = e0 * inv;
    if (lane < 16) a[lane + 32] = e1 * inv;
}

// ============================================================
// Weff written DIRECTLY into the fragment-uint4 layout.
// ============================================================
__global__ __launch_bounds__(256) void weff_kernel(const float* __restrict__ wproj)
{
    const int idx = blockIdx.x * 256 + threadIdx.x;
    if (idx >= B_ * C_ * C_) return;
    const int b = idx / (C_ * C_);
    const int r = idx % (C_ * C_);
    const int o = r / C_;
    const int j = r % C_;
    const int h = j / HC, d = j % HC;

    const float* wp = wproj + o * C_ + h * HC;
    const float* at = g_attn + ((b * 4 + h) * 48) * 48 + d;
    float s = 0.f;
#pragma unroll 8
    for (int cc = 0; cc < 48; cc++)
        s += wp[cc] * at[cc * 48];

    const int mtile = o / 96;
    const int mloc  = o % 96;
    const int wmh   = mloc / 48;
    const int rr    = mloc % 48;
    const int mt    = rr / 16;
    const int s16   = rr % 16;
    const int colsel = s16 >> 3;
    const int grp    = s16 & 7;
    const int it     = j >> 4;
    const int jr     = (j >> 1) & 7;
    const int rowsel = jr >> 2;
    const int qd     = jr & 3;
    const int lane   = grp * 4 + qd;
    const int reg    = rowsel * 2 + colsel;

    const size_t u4 = (size_t)(b * 2 + mtile) * TILE_U4 +
                      ((it * 3 + mt) * 2 + wmh) * 32 + lane;
    ((__half*)g_weffh)[u4 * 8 + reg * 2 + (j & 1)] = __float2half_rn(s);
}

// ============================================================
extern "C" void kernel_launch(void* const* d_in, const int* in_sizes, int n_in,
                              void* d_out, int out_size)
{
    const float *x = nullptr, *w_qkv = nullptr, *w_dw = nullptr,
                *temperature = nullptr, *w_proj = nullptr;
    for (int i = 0; i < n_in; i++) {
        switch (in_sizes[i]) {
            case 25165824: x           = (const float*)d_in[i]; break;
            case 110592:   w_qkv       = (const float*)d_in[i]; break;
            case 5184:     w_dw        = (const float*)d_in[i]; break;
            case 4:        temperature = (const float*)d_in[i]; break;
            case 36864:    w_proj      = (const float*)d_in[i]; break;
        }
    }
    float* out = (float*)d_out;

    __half *qkv, *dwq;
    uint4 *wqkvh, *weffh;
    cudaGetSymbolAddress((void**)&qkv,   g_qkv);
    cudaGetSymbolAddress((void**)&dwq,   g_dwq);
    cudaGetSymbolAddress((void**)&wqkvh, g_wqkvh);
    cudaGetSymbolAddress((void**)&weffh, g_weffh);

    // 0) pack W_qkv
    pack_w_kernel<<<(6 * TILE_U4 + 255) / 256, 256>>>(w_qkv);

    // 1) qkv[b] = W_qkv @ x[b]
    gemm_f16<false, true><<<dim3(C3 / BM, HW / BN, B_), 128>>>(
        wqkvh, x, qkv, (size_t)0, (size_t)C_ * HW, (size_t)C3 * HW);

    // 2) depthwise 3x3
    dwconv_kernel<<<dim3(2, C3, B_), 256>>>(w_dw);

    // 3) Gram via tensor cores (4th launch -> profiled this round)
    gram_kernel<<<dim3(NCH, 32), 128>>>();

    // 4) reduce partials
    reduce_kernel<<<(32 * PART_STRIDE + 255) / 256, 256>>>();

    // 5) scaled softmax
    softmax_kernel<<<32 * 48, 32>>>(temperature);

    // 6) Weff = W_proj @ attn, written packed
    weff_kernel<<<(B_ * C_ * C_ + 255) / 256, 256>>>(w_proj);

    // 7) out[b] = Weff[b] @ V[b]
    gemm_f16<true, false><<<dim3(C_ / BM, HW / BN, B_), 128>>>(
        weffh, dwq + (size_t)2 * C_ * HW, out,
        (size_t)(2 * TILE_U4), (size_t)C3 * HW, (size_t)C_ * HW);
}